// round 2
// baseline (speedup 1.0000x reference)
#include <cuda_runtime.h>
#include <mma.h>
using namespace nvcuda;

#define TSCALE 256
#define NS 32
#define NW 8
#define NTW 65536      // NS*TSCALE*NW  (sample_mask columns)
#define JTOT 4096      // B*TSCALE*NW   (GEMM N dim)
#define DIMX 512
#define H1 256
#define H3 512
#define H2 128
#define KTOT 8192      // H1*NS         (GEMM K dim)

// ---------------- scratch (device globals; no runtime alloc) ----------------
__device__ float d_h[2 * H1 * TSCALE];          // conv1 output, 512 KB
__device__ int   d_midx[NTW * 8];               // sparse mask indices
__device__ float d_mval[NTW * 8];               // sparse mask values
__device__ float d_S[(size_t)KTOT * JTOT];      // samp matrix, 134 MB
__device__ float d_Y[H3 * JTOT];                // r3d output, 8 MB
__device__ float d_F[H2 * JTOT];                // r2d output, 2 MB
__device__ float d_HT[H2 * JTOT];               // head temp, 2 MB

// ---------------- K1: conv1d(512->256,k=3,same) + bias ----------------
__global__ void conv1_kernel(const float* __restrict__ x,
                             const float* __restrict__ w,
                             const float* __restrict__ bias) {
    int b  = blockIdx.y;
    int o0 = blockIdx.x * 4;
    int t  = threadIdx.x;  // 256
    __shared__ float xs[8][TSCALE + 2];
    __shared__ float ws[4][8][3];
    float acc[4];
#pragma unroll
    for (int u = 0; u < 4; u++) acc[u] = bias[o0 + u];
    for (int i0 = 0; i0 < DIMX; i0 += 8) {
#pragma unroll
        for (int r = 0; r < 8; r++)
            xs[r][t + 1] = x[(b * DIMX + i0 + r) * TSCALE + t];
        if (t < 8) { xs[t][0] = 0.f; xs[t][TSCALE + 1] = 0.f; }
        if (t < 96) {
            int u = t / 24, rem = t % 24, r = rem / 3, k = rem % 3;
            ws[u][r][k] = w[((o0 + u) * DIMX + i0 + r) * 3 + k];
        }
        __syncthreads();
#pragma unroll
        for (int r = 0; r < 8; r++) {
            float xm = xs[r][t], x0 = xs[r][t + 1], xp = xs[r][t + 2];
#pragma unroll
            for (int u = 0; u < 4; u++)
                acc[u] += xm * ws[u][r][0] + x0 * ws[u][r][1] + xp * ws[u][r][2];
        }
        __syncthreads();
    }
#pragma unroll
    for (int u = 0; u < 4; u++)
        d_h[(b * H1 + o0 + u) * TSCALE + t] = acc[u];
}

// ---------------- generic GroupNorm(32 groups) + ReLU, in place ----------------
__device__ __forceinline__ float* gn_target(int id) {
    switch (id) {
        case 0: return d_h;
        case 1: return d_Y;
        case 2: return d_F;
        default: return d_HT;
    }
}

__global__ void gn_relu_kernel(int target_id,
                               const float* __restrict__ gamma,
                               const float* __restrict__ beta,
                               const float* __restrict__ prebias,
                               int cpg, int logL, int rstride, int boff) {
    float* data = gn_target(target_id);
    int g = blockIdx.x & 31;
    int b = blockIdx.x >> 5;
    int chan0 = g * cpg;
    int base = chan0 * rstride + b * boff;
    int L = 1 << logL;
    int N = cpg * L;
    int tid = threadIdx.x;
    float s = 0.f, sq = 0.f;
    for (int idx = tid; idx < N; idx += 256) {
        int r = idx >> logL, p = idx & (L - 1);
        float v = data[base + r * rstride + p];
        if (prebias) v += prebias[chan0 + r];
        s += v; sq += v * v;
    }
    __shared__ float sh[512];
    sh[tid] = s; sh[256 + tid] = sq;
    __syncthreads();
    for (int st = 128; st > 0; st >>= 1) {
        if (tid < st) { sh[tid] += sh[tid + st]; sh[256 + tid] += sh[256 + tid + st]; }
        __syncthreads();
    }
    float mean = sh[0] / (float)N;
    float var  = sh[256] / (float)N - mean * mean;
    float inv  = rsqrtf(var + 1e-5f);
    for (int idx = tid; idx < N; idx += 256) {
        int r = idx >> logL, p = idx & (L - 1);
        int off = base + r * rstride + p;
        float v = data[off];
        if (prebias) v += prebias[chan0 + r];
        v = (v - mean) * inv * gamma[chan0 + r] + beta[chan0 + r];
        data[off] = fmaxf(v, 0.f);
    }
}

// ---------------- K3: extract sparse structure of sample_mask ----------------
// Each column (n,t,w) of the (256 x 65536) mask has <= 6 nonzeros.
__global__ void scan_mask_kernel(const float* __restrict__ mask) {
    int j = blockIdx.x * 256 + threadIdx.x;
    int idxs[8]; float vals[8];
    int cnt = 0;
    for (int tin = 0; tin < TSCALE; tin++) {
        float v = mask[tin * NTW + j];
        if (v != 0.f && cnt < 8) { idxs[cnt] = tin; vals[cnt] = v; cnt++; }
    }
#pragma unroll
    for (int s = 0; s < 8; s++) {
        d_midx[j * 8 + s] = (s < cnt) ? idxs[s] : 0;
        d_mval[j * 8 + s] = (s < cnt) ? vals[s] : 0.f;
    }
}

// ---------------- K4: build S[k=(c,n)][j=(b,t,w)] via sparse gather ----------------
// block = (t-chunk of 16, n); threads 256 = (b,tl,w)
__global__ void samp_build_kernel() {
    int n  = blockIdx.y;
    int t0 = blockIdx.x * 16;
    int tid = threadIdx.x;
    __shared__ int   sidx[128][9];
    __shared__ float sval[128][9];
    __shared__ float hs[2][TSCALE];
    if (tid < 128) {
        int jm = n * 2048 + t0 * 8 + tid;  // tid = tl*8+w
#pragma unroll
        for (int s = 0; s < 8; s++) {
            sidx[tid][s] = d_midx[jm * 8 + s];
            sval[tid][s] = d_mval[jm * 8 + s];
        }
    }
    int bb  = tid >> 7;
    int col = tid & 127;
    int jout = bb * 2048 + t0 * 8 + col;
    for (int c = 0; c < H1; c++) {
        __syncthreads();
        hs[0][tid] = d_h[c * TSCALE + tid];
        hs[1][tid] = d_h[(H1 + c) * TSCALE + tid];
        __syncthreads();
        float acc = 0.f;
#pragma unroll
        for (int s = 0; s < 8; s++)
            acc += sval[col][s] * hs[bb][sidx[col][s]];
        d_S[(size_t)(c * NS + n) * JTOT + jout] = acc;
    }
}

// ---------------- K5: r3d GEMM  Y[512x4096] = W[512x8192] * S[8192x4096]  (tf32 wmma) ----
#define BM 128
#define BN 128
#define BK 32
__global__ void __launch_bounds__(256) r3d_gemm_kernel(const float* __restrict__ A) {
    __shared__ float As[BM][BK + 4];   // 128x36
    __shared__ float Bs[BK][BN + 4];   // 32x132
    int m0 = blockIdx.x * BM;
    int n0 = blockIdx.y * BN;
    int tid = threadIdx.x;
    int warp = tid >> 5;
    int wm = warp & 1, wn = warp >> 1;  // 2x4 warp grid, warp tile 64x32
    wmma::fragment<wmma::accumulator, 16, 16, 8, float> acc[4][2];
#pragma unroll
    for (int i = 0; i < 4; i++)
#pragma unroll
        for (int j = 0; j < 2; j++) wmma::fill_fragment(acc[i][j], 0.f);

    for (int k0 = 0; k0 < KTOT; k0 += BK) {
#pragma unroll
        for (int l = 0; l < 4; l++) {
            int e = tid + l * 256;       // 1024 float4s of A tile
            int r = e >> 3, c4 = e & 7;
            float4 v = *reinterpret_cast<const float4*>(&A[(size_t)(m0 + r) * KTOT + k0 + c4 * 4]);
            *reinterpret_cast<float4*>(&As[r][c4 * 4]) = v;
        }
#pragma unroll
        for (int l = 0; l < 4; l++) {
            int e = tid + l * 256;       // 1024 float4s of B tile
            int r = e >> 5, c4 = e & 31;
            float4 v = *reinterpret_cast<const float4*>(&d_S[(size_t)(k0 + r) * JTOT + n0 + c4 * 4]);
            *reinterpret_cast<float4*>(&Bs[r][c4 * 4]) = v;
        }
        __syncthreads();
#pragma unroll
        for (int kk = 0; kk < BK; kk += 8) {
            wmma::fragment<wmma::matrix_a, 16, 16, 8, wmma::precision::tf32, wmma::row_major> af[4];
            wmma::fragment<wmma::matrix_b, 16, 16, 8, wmma::precision::tf32, wmma::row_major> bf[2];
#pragma unroll
            for (int i = 0; i < 4; i++) {
                wmma::load_matrix_sync(af[i], &As[wm * 64 + i * 16][kk], BK + 4);
#pragma unroll
                for (int e = 0; e < af[i].num_elements; e++)
                    af[i].x[e] = wmma::__float_to_tf32(af[i].x[e]);
            }
#pragma unroll
            for (int j = 0; j < 2; j++) {
                wmma::load_matrix_sync(bf[j], &Bs[kk][wn * 32 + j * 16], BN + 4);
#pragma unroll
                for (int e = 0; e < bf[j].num_elements; e++)
                    bf[j].x[e] = wmma::__float_to_tf32(bf[j].x[e]);
            }
#pragma unroll
            for (int i = 0; i < 4; i++)
#pragma unroll
                for (int j = 0; j < 2; j++)
                    wmma::mma_sync(acc[i][j], af[i], bf[j], acc[i][j]);
        }
        __syncthreads();
    }
#pragma unroll
    for (int i = 0; i < 4; i++)
#pragma unroll
        for (int j = 0; j < 2; j++)
            wmma::store_matrix_sync(&d_Y[(m0 + wm * 64 + i * 16) * JTOT + n0 + wn * 32 + j * 16],
                                    acc[i][j], JTOT, wmma::mem_row_major);
}

// ---------------- K7: r2d 1x1 conv (128x512 GEMM) + bias ----------------
__global__ void r2d_kernel(const float* __restrict__ w2, const float* __restrict__ b2) {
    __shared__ float ws[16][512];  // 32 KB
    int j  = blockIdx.x * 256 + threadIdx.x;
    int o0 = blockIdx.y * 16;
    for (int e = threadIdx.x; e < 16 * 512; e += 256) {
        int o = e >> 9, k = e & 511;
        ws[o][k] = w2[(o0 + o) * 512 + k];
    }
    __syncthreads();
    float acc[16];
#pragma unroll
    for (int o = 0; o < 16; o++) acc[o] = b2[o0 + o];
    for (int k = 0; k < 512; k++) {
        float yv = d_Y[k * JTOT + j];
#pragma unroll
        for (int o = 0; o < 16; o++) acc[o] += ws[o][k] * yv;
    }
#pragma unroll
    for (int o = 0; o < 16; o++) d_F[(o0 + o) * JTOT + j] = acc[o];
}

// ---------------- K9: head conv3x3(128->128, same) + bias ----------------
// grid (t-tile 16, o-tile 8x16, b 2); 128 threads = (tl 16, w 8)
__global__ void head_conv3_kernel(const float* __restrict__ w, const float* __restrict__ bias) {
    int t0 = blockIdx.x * 16;
    int o0 = blockIdx.y * 16;
    int b  = blockIdx.z;
    int tid = threadIdx.x;
    int tl = tid >> 3, wq = tid & 7;
    __shared__ float fs[4][18][10];
    __shared__ float ws[16][4][9];
    float acc[16];
#pragma unroll
    for (int o = 0; o < 16; o++) acc[o] = bias[o0 + o];
    for (int i0 = 0; i0 < H2; i0 += 4) {
        __syncthreads();
        for (int e = tid; e < 4 * 18 * 8; e += 128) {
            int ii = e / 144, rem = e % 144, tr = rem >> 3, wl = rem & 7;
            int tg = t0 - 1 + tr;
            float v = 0.f;
            if (tg >= 0 && tg < 256) v = d_F[(i0 + ii) * JTOT + b * 2048 + tg * 8 + wl];
            fs[ii][tr][1 + wl] = v;
        }
        for (int e = tid; e < 4 * 18 * 2; e += 128) {
            int ii = e / 36, rem = e % 36, tr = rem >> 1, side = rem & 1;
            fs[ii][tr][side ? 9 : 0] = 0.f;
        }
        for (int e = tid; e < 16 * 4 * 9; e += 128) {
            int o = e / 36, rem = e % 36, ii = rem / 9, kk = rem % 9;
            ws[o][ii][kk] = w[((o0 + o) * H2 + i0 + ii) * 9 + kk];
        }
        __syncthreads();
#pragma unroll
        for (int ii = 0; ii < 4; ii++) {
            float f00 = fs[ii][tl][wq],     f01 = fs[ii][tl][wq + 1],     f02 = fs[ii][tl][wq + 2];
            float f10 = fs[ii][tl + 1][wq], f11 = fs[ii][tl + 1][wq + 1], f12 = fs[ii][tl + 1][wq + 2];
            float f20 = fs[ii][tl + 2][wq], f21 = fs[ii][tl + 2][wq + 1], f22 = fs[ii][tl + 2][wq + 2];
#pragma unroll
            for (int o = 0; o < 16; o++) {
                const float* W9 = ws[o][ii];
                acc[o] += f00 * W9[0] + f01 * W9[1] + f02 * W9[2]
                        + f10 * W9[3] + f11 * W9[4] + f12 * W9[5]
                        + f20 * W9[6] + f21 * W9[7] + f22 * W9[8];
            }
        }
    }
    int t = t0 + tl;
#pragma unroll
    for (int o = 0; o < 16; o++)
        d_HT[(o0 + o) * JTOT + b * 2048 + t * 8 + wq] = acc[o];
}

// ---------------- K11: head 1x1 -> sigmoid -> out ----------------
__global__ void head_final_kernel(const float* __restrict__ w2, const float* __restrict__ b2,
                                  float* __restrict__ out, int ch) {
    int j = blockIdx.x * 256 + threadIdx.x;  // 0..4095
    float acc = b2[0];
    for (int i = 0; i < H2; i++) acc += w2[i] * d_HT[i * JTOT + j];
    float sg = 1.f / (1.f + expf(-acc));
    int b = j >> 11, rem = j & 2047;
    out[((b * 2 + ch) << 11) + rem] = sg;
}

// ---------------- launch ----------------
extern "C" void kernel_launch(void* const* d_in, const int* in_sizes, int n_in,
                              void* d_out, int out_size) {
    const float* x     = (const float*)d_in[0];
    const float* mask  = (const float*)d_in[1];
    const float* c1_w  = (const float*)d_in[2];
    const float* c1_b  = (const float*)d_in[3];
    const float* gn1_g = (const float*)d_in[4];
    const float* gn1_b = (const float*)d_in[5];
    const float* r3d_w = (const float*)d_in[6];
    const float* r3d_b = (const float*)d_in[7];
    const float* gn3_g = (const float*)d_in[8];
    const float* gn3_b = (const float*)d_in[9];
    const float* r2d_w = (const float*)d_in[10];
    const float* r2d_b = (const float*)d_in[11];
    const float* gn2_g = (const float*)d_in[12];
    const float* gn2_b = (const float*)d_in[13];
    const float* s1_w  = (const float*)d_in[14];
    const float* s1_b  = (const float*)d_in[15];
    const float* sgn_g = (const float*)d_in[16];
    const float* sgn_b = (const float*)d_in[17];
    const float* s2_w  = (const float*)d_in[18];
    const float* s2_b  = (const float*)d_in[19];
    const float* e1_w  = (const float*)d_in[20];
    const float* e1_b  = (const float*)d_in[21];
    const float* egn_g = (const float*)d_in[22];
    const float* egn_b = (const float*)d_in[23];
    const float* e2_w  = (const float*)d_in[24];
    const float* e2_b  = (const float*)d_in[25];
    float* out = (float*)d_out;

    // conv1 + GN1 + ReLU  -> d_h
    conv1_kernel<<<dim3(64, 2), 256>>>(x, c1_w, c1_b);
    gn_relu_kernel<<<64, 256>>>(0, gn1_g, gn1_b, nullptr, 8, 8, TSCALE, H1 * TSCALE);

    // sparse mask structure + samp matrix S
    scan_mask_kernel<<<256, 256>>>(mask);
    samp_build_kernel<<<dim3(16, 32), 256>>>();

    // r3d GEMM -> d_Y, then GN3(+bias) + ReLU
    r3d_gemm_kernel<<<dim3(4, 32), 256>>>(r3d_w);
    gn_relu_kernel<<<64, 256>>>(1, gn3_g, gn3_b, r3d_b, 16, 11, JTOT, 2048);

    // r2d 1x1 -> d_F, GN2 + ReLU
    r2d_kernel<<<dim3(16, 8), 256>>>(r2d_w, r2d_b);
    gn_relu_kernel<<<64, 256>>>(2, gn2_g, gn2_b, nullptr, 4, 11, JTOT, 2048);

    // start head
    head_conv3_kernel<<<dim3(16, 8, 2), 128>>>(s1_w, s1_b);
    gn_relu_kernel<<<64, 256>>>(3, sgn_g, sgn_b, nullptr, 4, 11, JTOT, 2048);
    head_final_kernel<<<16, 256>>>(s2_w, s2_b, out, 0);

    // end head
    head_conv3_kernel<<<dim3(16, 8, 2), 128>>>(e1_w, e1_b);
    gn_relu_kernel<<<64, 256>>>(3, egn_g, egn_b, nullptr, 4, 11, JTOT, 2048);
    head_final_kernel<<<16, 256>>>(e2_w, e2_b, out, 1);
}

// round 3
// speedup vs baseline: 1.1743x; 1.1743x over previous
#include <cuda_runtime.h>
#include <mma.h>
using namespace nvcuda;

#define TSCALE 256
#define NS 32
#define NW 8
#define NTW 65536      // NS*TSCALE*NW  (sample_mask columns)
#define JTOT 4096      // B*TSCALE*NW   (GEMM N dim)
#define DIMX 512
#define H1 256
#define H3 512
#define H2 128
#define KTOT 8192      // H1*NS         (GEMM K dim)

// ---------------- scratch (device globals; no runtime alloc) ----------------
__device__ float d_h[2 * H1 * TSCALE];          // conv1 output, 512 KB
__device__ int   d_midx[NTW * 8];               // sparse mask indices
__device__ float d_mval[NTW * 8];               // sparse mask values
__device__ float d_S[(size_t)KTOT * JTOT];      // samp matrix, 134 MB
__device__ float d_Y[H3 * JTOT];                // r3d output, 8 MB
__device__ float d_F[H2 * JTOT];                // r2d output, 2 MB
__device__ float d_HT[H2 * JTOT];               // head temp, 2 MB

// ---------------- K1: conv1d(512->256,k=3,same) + bias ----------------
__global__ void conv1_kernel(const float* __restrict__ x,
                             const float* __restrict__ w,
                             const float* __restrict__ bias) {
    int b  = blockIdx.y;
    int o0 = blockIdx.x * 4;
    int t  = threadIdx.x;  // 256
    __shared__ float xs[8][TSCALE + 2];
    __shared__ float ws[4][8][3];
    float acc[4];
#pragma unroll
    for (int u = 0; u < 4; u++) acc[u] = bias[o0 + u];
    for (int i0 = 0; i0 < DIMX; i0 += 8) {
#pragma unroll
        for (int r = 0; r < 8; r++)
            xs[r][t + 1] = x[(b * DIMX + i0 + r) * TSCALE + t];
        if (t < 8) { xs[t][0] = 0.f; xs[t][TSCALE + 1] = 0.f; }
        if (t < 96) {
            int u = t / 24, rem = t % 24, r = rem / 3, k = rem % 3;
            ws[u][r][k] = w[((o0 + u) * DIMX + i0 + r) * 3 + k];
        }
        __syncthreads();
#pragma unroll
        for (int r = 0; r < 8; r++) {
            float xm = xs[r][t], x0 = xs[r][t + 1], xp = xs[r][t + 2];
#pragma unroll
            for (int u = 0; u < 4; u++)
                acc[u] += xm * ws[u][r][0] + x0 * ws[u][r][1] + xp * ws[u][r][2];
        }
        __syncthreads();
    }
#pragma unroll
    for (int u = 0; u < 4; u++)
        d_h[(b * H1 + o0 + u) * TSCALE + t] = acc[u];
}

// ---------------- generic GroupNorm(32 groups) + ReLU, in place ----------------
__device__ __forceinline__ float* gn_target(int id) {
    switch (id) {
        case 0: return d_h;
        case 1: return d_Y;
        case 2: return d_F;
        default: return d_HT;
    }
}

__global__ void gn_relu_kernel(int target_id,
                               const float* __restrict__ gamma,
                               const float* __restrict__ beta,
                               const float* __restrict__ prebias,
                               int cpg, int logL, int rstride, int boff) {
    float* data = gn_target(target_id);
    int g = blockIdx.x & 31;
    int b = blockIdx.x >> 5;
    int chan0 = g * cpg;
    int base = chan0 * rstride + b * boff;
    int L = 1 << logL;
    int N = cpg * L;
    int tid = threadIdx.x;
    float s = 0.f, sq = 0.f;
    for (int idx = tid; idx < N; idx += 256) {
        int r = idx >> logL, p = idx & (L - 1);
        float v = data[base + r * rstride + p];
        if (prebias) v += prebias[chan0 + r];
        s += v; sq += v * v;
    }
    __shared__ float sh[512];
    sh[tid] = s; sh[256 + tid] = sq;
    __syncthreads();
    for (int st = 128; st > 0; st >>= 1) {
        if (tid < st) { sh[tid] += sh[tid + st]; sh[256 + tid] += sh[256 + tid + st]; }
        __syncthreads();
    }
    float mean = sh[0] / (float)N;
    float var  = sh[256] / (float)N - mean * mean;
    float inv  = rsqrtf(var + 1e-5f);
    for (int idx = tid; idx < N; idx += 256) {
        int r = idx >> logL, p = idx & (L - 1);
        int off = base + r * rstride + p;
        float v = data[off];
        if (prebias) v += prebias[chan0 + r];
        v = (v - mean) * inv * gamma[chan0 + r] + beta[chan0 + r];
        data[off] = fmaxf(v, 0.f);
    }
}

// ---------------- K3: extract sparse structure of sample_mask ----------------
// Each column (n,t,w) of the (256 x 65536) mask has <= 6 nonzeros (3 samples x 2 cells).
__global__ void scan_mask_kernel(const float* __restrict__ mask) {
    int j = blockIdx.x * 256 + threadIdx.x;
    int idxs[8]; float vals[8];
    int cnt = 0;
    for (int tin = 0; tin < TSCALE; tin++) {
        float v = mask[tin * NTW + j];
        if (v != 0.f && cnt < 8) { idxs[cnt] = tin; vals[cnt] = v; cnt++; }
    }
#pragma unroll
    for (int s = 0; s < 8; s++) {
        d_midx[j * 8 + s] = (s < cnt) ? idxs[s] : 0;
        d_mval[j * 8 + s] = (s < cnt) ? vals[s] : 0.f;
    }
}

// ---------------- K4: build S[k=(c,n)][j=(b,t,w)] via sparse gather ----------------
// Taps live in REGISTERS; 4 channels per smem fill. block 256 = (b, 128 (t,w) cols)
__global__ void __launch_bounds__(256) samp_build_kernel() {
    int n  = blockIdx.y;
    int t0 = blockIdx.x * 16;
    int tid = threadIdx.x;
    int bb  = tid >> 7;         // batch
    int col = tid & 127;        // tl*8 + w
    int jm = n * 2048 + t0 * 8 + col;   // mask column (n,t,w)
    int   idx[6]; float val[6];
#pragma unroll
    for (int s = 0; s < 6; s++) {
        idx[s] = d_midx[jm * 8 + s];
        val[s] = d_mval[jm * 8 + s];
    }
    __shared__ float hs[2][4][TSCALE];  // 8 KB
    int jout = bb * 2048 + t0 * 8 + col;
    for (int c0 = 0; c0 < H1; c0 += 4) {
        __syncthreads();
        // fill 2b x 4c x 256 floats = 512 float4s with 256 threads
#pragma unroll
        for (int l = 0; l < 2; l++) {
            int e = tid + l * 256;
            int b_ = e >> 8, rem = e & 255, cc = rem >> 6, p4 = rem & 63;
            ((float4*)hs[b_][cc])[p4] =
                ((const float4*)&d_h[(b_ * H1 + c0 + cc) * TSCALE])[p4];
        }
        __syncthreads();
#pragma unroll
        for (int cc = 0; cc < 4; cc++) {
            float acc = 0.f;
#pragma unroll
            for (int s = 0; s < 6; s++)
                acc += val[s] * hs[bb][cc][idx[s]];
            d_S[(size_t)((c0 + cc) * NS + n) * JTOT + jout] = acc;
        }
    }
}

// ---------------- K5: r3d GEMM  Y[512x4096] = W[512x8192] * S[8192x4096] ----------------
// tf32 wmma, 4-stage cp.async pipeline, no explicit cvt (HMMA truncates f32->tf32).
#define BM 128
#define BN 128
#define BK 32
#define STAGES 4
#define AS_STRIDE (BM * 36)    // 4608 floats per stage
#define BS_STRIDE (BK * 132)   // 4224 floats per stage
#define NKT (KTOT / BK)        // 256 k-tiles

__device__ __forceinline__ void cp16(void* sdst, const void* gsrc) {
    unsigned saddr = (unsigned)__cvta_generic_to_shared(sdst);
    asm volatile("cp.async.cg.shared.global [%0], [%1], 16;\n"
                 :: "r"(saddr), "l"(gsrc));
}

__global__ void __launch_bounds__(256) r3d_gemm_kernel(const float* __restrict__ A) {
    extern __shared__ float smem[];
    float* As = smem;                         // STAGES x 128x36
    float* Bs = smem + STAGES * AS_STRIDE;    // STAGES x 32x132
    int m0 = blockIdx.x * BM;
    int n0 = blockIdx.y * BN;
    int tid = threadIdx.x;
    int warp = tid >> 5;
    int wm = warp & 1, wn = warp >> 1;        // 2x4 warp grid, warp tile 64x32

    wmma::fragment<wmma::accumulator, 16, 16, 8, float> acc[4][2];
#pragma unroll
    for (int i = 0; i < 4; i++)
#pragma unroll
        for (int j = 0; j < 2; j++) wmma::fill_fragment(acc[i][j], 0.f);

    auto issue = [&](int s, int kt) {
        int k0 = kt * BK;
        float* as = As + s * AS_STRIDE;
#pragma unroll
        for (int l = 0; l < 4; l++) {
            int q = tid + l * 256;
            int r = q >> 3, c = (q & 7) << 2;
            cp16(as + r * 36 + c, A + (size_t)(m0 + r) * KTOT + k0 + c);
        }
        float* bs = Bs + s * BS_STRIDE;
#pragma unroll
        for (int l = 0; l < 4; l++) {
            int q = tid + l * 256;
            int r = q >> 5, c = (q & 31) << 2;
            cp16(bs + r * 132 + c, d_S + (size_t)(k0 + r) * JTOT + n0 + c);
        }
        asm volatile("cp.async.commit_group;\n");
    };

#pragma unroll
    for (int s = 0; s < STAGES - 1; s++) issue(s, s);

    for (int kt = 0; kt < NKT; kt++) {
        asm volatile("cp.async.wait_group %0;\n" :: "n"(STAGES - 2));
        __syncthreads();
        int s = kt & (STAGES - 1);
        float* as = As + s * AS_STRIDE;
        float* bs = Bs + s * BS_STRIDE;
#pragma unroll
        for (int kk = 0; kk < BK; kk += 8) {
            wmma::fragment<wmma::matrix_a, 16, 16, 8, wmma::precision::tf32, wmma::row_major> af[4];
            wmma::fragment<wmma::matrix_b, 16, 16, 8, wmma::precision::tf32, wmma::row_major> bf[2];
#pragma unroll
            for (int i = 0; i < 4; i++)
                wmma::load_matrix_sync(af[i], as + (wm * 64 + i * 16) * 36 + kk, 36);
#pragma unroll
            for (int j = 0; j < 2; j++)
                wmma::load_matrix_sync(bf[j], bs + kk * 132 + wn * 32 + j * 16, 132);
#pragma unroll
            for (int i = 0; i < 4; i++)
#pragma unroll
                for (int j = 0; j < 2; j++)
                    wmma::mma_sync(acc[i][j], af[i], bf[j], acc[i][j]);
        }
        __syncthreads();
        if (kt + STAGES - 1 < NKT) issue((kt + STAGES - 1) & (STAGES - 1), kt + STAGES - 1);
    }
#pragma unroll
    for (int i = 0; i < 4; i++)
#pragma unroll
        for (int j = 0; j < 2; j++)
            wmma::store_matrix_sync(&d_Y[(m0 + wm * 64 + i * 16) * JTOT + n0 + wn * 32 + j * 16],
                                    acc[i][j], JTOT, wmma::mem_row_major);
}

// ---------------- K7: r2d 1x1 conv (128x512 GEMM) + bias ----------------
__global__ void r2d_kernel(const float* __restrict__ w2, const float* __restrict__ b2) {
    __shared__ float ws[16][512];  // 32 KB
    int j  = blockIdx.x * 256 + threadIdx.x;
    int o0 = blockIdx.y * 16;
    for (int e = threadIdx.x; e < 16 * 512; e += 256) {
        int o = e >> 9, k = e & 511;
        ws[o][k] = w2[(o0 + o) * 512 + k];
    }
    __syncthreads();
    float acc[16];
#pragma unroll
    for (int o = 0; o < 16; o++) acc[o] = b2[o0 + o];
    for (int k = 0; k < 512; k++) {
        float yv = d_Y[k * JTOT + j];
#pragma unroll
        for (int o = 0; o < 16; o++) acc[o] += ws[o][k] * yv;
    }
#pragma unroll
    for (int o = 0; o < 16; o++) d_F[(o0 + o) * JTOT + j] = acc[o];
}

// ---------------- K9: head conv3x3(128->128, same) + bias ----------------
__global__ void head_conv3_kernel(const float* __restrict__ w, const float* __restrict__ bias) {
    int t0 = blockIdx.x * 16;
    int o0 = blockIdx.y * 16;
    int b  = blockIdx.z;
    int tid = threadIdx.x;
    int tl = tid >> 3, wq = tid & 7;
    __shared__ float fs[4][18][10];
    __shared__ float ws[16][4][9];
    float acc[16];
#pragma unroll
    for (int o = 0; o < 16; o++) acc[o] = bias[o0 + o];
    for (int i0 = 0; i0 < H2; i0 += 4) {
        __syncthreads();
        for (int e = tid; e < 4 * 18 * 8; e += 128) {
            int ii = e / 144, rem = e % 144, tr = rem >> 3, wl = rem & 7;
            int tg = t0 - 1 + tr;
            float v = 0.f;
            if (tg >= 0 && tg < 256) v = d_F[(i0 + ii) * JTOT + b * 2048 + tg * 8 + wl];
            fs[ii][tr][1 + wl] = v;
        }
        for (int e = tid; e < 4 * 18 * 2; e += 128) {
            int ii = e / 36, rem = e % 36, tr = rem >> 1, side = rem & 1;
            fs[ii][tr][side ? 9 : 0] = 0.f;
        }
        for (int e = tid; e < 16 * 4 * 9; e += 128) {
            int o = e / 36, rem = e % 36, ii = rem / 9, kk = rem % 9;
            ws[o][ii][kk] = w[((o0 + o) * H2 + i0 + ii) * 9 + kk];
        }
        __syncthreads();
#pragma unroll
        for (int ii = 0; ii < 4; ii++) {
            float f00 = fs[ii][tl][wq],     f01 = fs[ii][tl][wq + 1],     f02 = fs[ii][tl][wq + 2];
            float f10 = fs[ii][tl + 1][wq], f11 = fs[ii][tl + 1][wq + 1], f12 = fs[ii][tl + 1][wq + 2];
            float f20 = fs[ii][tl + 2][wq], f21 = fs[ii][tl + 2][wq + 1], f22 = fs[ii][tl + 2][wq + 2];
#pragma unroll
            for (int o = 0; o < 16; o++) {
                const float* W9 = ws[o][ii];
                acc[o] += f00 * W9[0] + f01 * W9[1] + f02 * W9[2]
                        + f10 * W9[3] + f11 * W9[4] + f12 * W9[5]
                        + f20 * W9[6] + f21 * W9[7] + f22 * W9[8];
            }
        }
    }
    int t = t0 + tl;
#pragma unroll
    for (int o = 0; o < 16; o++)
        d_HT[(o0 + o) * JTOT + b * 2048 + t * 8 + wq] = acc[o];
}

// ---------------- K11: head 1x1 -> sigmoid -> out ----------------
__global__ void head_final_kernel(const float* __restrict__ w2, const float* __restrict__ b2,
                                  float* __restrict__ out, int ch) {
    int j = blockIdx.x * 256 + threadIdx.x;  // 0..4095
    float acc = b2[0];
    for (int i = 0; i < H2; i++) acc += w2[i] * d_HT[i * JTOT + j];
    float sg = 1.f / (1.f + expf(-acc));
    int b = j >> 11, rem = j & 2047;
    out[((b * 2 + ch) << 11) + rem] = sg;
}

// ---------------- launch ----------------
extern "C" void kernel_launch(void* const* d_in, const int* in_sizes, int n_in,
                              void* d_out, int out_size) {
    const float* x     = (const float*)d_in[0];
    const float* mask  = (const float*)d_in[1];
    const float* c1_w  = (const float*)d_in[2];
    const float* c1_b  = (const float*)d_in[3];
    const float* gn1_g = (const float*)d_in[4];
    const float* gn1_b = (const float*)d_in[5];
    const float* r3d_w = (const float*)d_in[6];
    const float* r3d_b = (const float*)d_in[7];
    const float* gn3_g = (const float*)d_in[8];
    const float* gn3_b = (const float*)d_in[9];
    const float* r2d_w = (const float*)d_in[10];
    const float* r2d_b = (const float*)d_in[11];
    const float* gn2_g = (const float*)d_in[12];
    const float* gn2_b = (const float*)d_in[13];
    const float* s1_w  = (const float*)d_in[14];
    const float* s1_b  = (const float*)d_in[15];
    const float* sgn_g = (const float*)d_in[16];
    const float* sgn_b = (const float*)d_in[17];
    const float* s2_w  = (const float*)d_in[18];
    const float* s2_b  = (const float*)d_in[19];
    const float* e1_w  = (const float*)d_in[20];
    const float* e1_b  = (const float*)d_in[21];
    const float* egn_g = (const float*)d_in[22];
    const float* egn_b = (const float*)d_in[23];
    const float* e2_w  = (const float*)d_in[24];
    const float* e2_b  = (const float*)d_in[25];
    float* out = (float*)d_out;

    static bool attr_set = false;
    const int gemm_smem = STAGES * (AS_STRIDE + BS_STRIDE) * (int)sizeof(float);
    if (!attr_set) {
        cudaFuncSetAttribute(r3d_gemm_kernel,
                             cudaFuncAttributeMaxDynamicSharedMemorySize, gemm_smem);
        attr_set = true;
    }

    // conv1 + GN1 + ReLU  -> d_h
    conv1_kernel<<<dim3(64, 2), 256>>>(x, c1_w, c1_b);
    gn_relu_kernel<<<64, 256>>>(0, gn1_g, gn1_b, nullptr, 8, 8, TSCALE, H1 * TSCALE);

    // sparse mask structure + samp matrix S
    scan_mask_kernel<<<256, 256>>>(mask);
    samp_build_kernel<<<dim3(16, 32), 256>>>();

    // r3d GEMM -> d_Y, then GN3(+bias) + ReLU
    r3d_gemm_kernel<<<dim3(4, 32), 256, gemm_smem>>>(r3d_w);
    gn_relu_kernel<<<64, 256>>>(1, gn3_g, gn3_b, r3d_b, 16, 11, JTOT, 2048);

    // r2d 1x1 -> d_F, GN2 + ReLU
    r2d_kernel<<<dim3(16, 8), 256>>>(r2d_w, r2d_b);
    gn_relu_kernel<<<64, 256>>>(2, gn2_g, gn2_b, nullptr, 4, 11, JTOT, 2048);

    // start head
    head_conv3_kernel<<<dim3(16, 8, 2), 128>>>(s1_w, s1_b);
    gn_relu_kernel<<<64, 256>>>(3, sgn_g, sgn_b, nullptr, 4, 11, JTOT, 2048);
    head_final_kernel<<<16, 256>>>(s2_w, s2_b, out, 0);

    // end head
    head_conv3_kernel<<<dim3(16, 8, 2), 128>>>(e1_w, e1_b);
    gn_relu_kernel<<<64, 256>>>(3, egn_g, egn_b, nullptr, 4, 11, JTOT, 2048);
    head_final_kernel<<<16, 256>>>(e2_w, e2_b, out, 1);
}

// round 4
// speedup vs baseline: 2.1221x; 1.8071x over previous
#include <cuda_runtime.h>
#include <mma.h>
using namespace nvcuda;

#define TSCALE 256
#define NS 32
#define NW 8
#define NTW 65536      // NS*TSCALE*NW  (sample_mask columns)
#define JTOT 4096      // B*TSCALE*NW
#define DIMX 512
#define H1 256
#define H3 512
#define H2 128
#define UCOLS 16384    // NS*H3  (U-GEMM N dim)

// ---------------- scratch (device globals; no runtime alloc) ----------------
__device__ float d_h[2 * H1 * TSCALE];          // conv1 output [b][c][t], 512 KB
__device__ float d_hT[2 * TSCALE * H1];         // transposed [(b,t)][c], 512 KB
__device__ float d_WT[H1 * UCOLS];              // r3d_w transposed [c][(n,o)], 16.8 MB
__device__ float d_U[(size_t)512 * UCOLS];      // U[(b,tin)][(n,o)], 33.5 MB
__device__ int   d_midx[NTW * 8];               // sparse mask indices
__device__ float d_mval[NTW * 8];               // sparse mask values
__device__ float d_Y[(size_t)JTOT * H3];        // Y2[(b,t,w)][o], 8 MB
__device__ float d_F[H2 * JTOT];                // r2d output [h2][j], 2 MB
__device__ float d_HT[H2 * JTOT];               // head temp, 2 MB

// ---------------- K1: conv1d(512->256,k=3,same) + bias ----------------
__global__ void conv1_kernel(const float* __restrict__ x,
                             const float* __restrict__ w,
                             const float* __restrict__ bias) {
    int b  = blockIdx.y;
    int o0 = blockIdx.x * 4;
    int t  = threadIdx.x;  // 256
    __shared__ float xs[8][TSCALE + 2];
    __shared__ float ws[4][8][3];
    float acc[4];
#pragma unroll
    for (int u = 0; u < 4; u++) acc[u] = bias[o0 + u];
    for (int i0 = 0; i0 < DIMX; i0 += 8) {
#pragma unroll
        for (int r = 0; r < 8; r++)
            xs[r][t + 1] = x[(b * DIMX + i0 + r) * TSCALE + t];
        if (t < 8) { xs[t][0] = 0.f; xs[t][TSCALE + 1] = 0.f; }
        if (t < 96) {
            int u = t / 24, rem = t % 24, r = rem / 3, k = rem % 3;
            ws[u][r][k] = w[((o0 + u) * DIMX + i0 + r) * 3 + k];
        }
        __syncthreads();
#pragma unroll
        for (int r = 0; r < 8; r++) {
            float xm = xs[r][t], x0 = xs[r][t + 1], xp = xs[r][t + 2];
#pragma unroll
            for (int u = 0; u < 4; u++)
                acc[u] += xm * ws[u][r][0] + x0 * ws[u][r][1] + xp * ws[u][r][2];
        }
        __syncthreads();
    }
#pragma unroll
    for (int u = 0; u < 4; u++)
        d_h[(b * H1 + o0 + u) * TSCALE + t] = acc[u];
}

// ---------------- GroupNorm(32 groups) + ReLU, in place (layout [ch][j]) ----------------
__device__ __forceinline__ float* gn_target(int id) {
    switch (id) {
        case 0: return d_h;
        case 2: return d_F;
        default: return d_HT;
    }
}

__global__ void gn_relu_kernel(int target_id,
                               const float* __restrict__ gamma,
                               const float* __restrict__ beta,
                               int cpg, int logL, int rstride, int boff) {
    float* data = gn_target(target_id);
    int g = blockIdx.x & 31;
    int b = blockIdx.x >> 5;
    int chan0 = g * cpg;
    int base = chan0 * rstride + b * boff;
    int L = 1 << logL;
    int N = cpg * L;
    int tid = threadIdx.x;
    float s = 0.f, sq = 0.f;
    for (int idx = tid; idx < N; idx += 256) {
        int r = idx >> logL, p = idx & (L - 1);
        float v = data[base + r * rstride + p];
        s += v; sq += v * v;
    }
    __shared__ float sh[512];
    sh[tid] = s; sh[256 + tid] = sq;
    __syncthreads();
    for (int st = 128; st > 0; st >>= 1) {
        if (tid < st) { sh[tid] += sh[tid + st]; sh[256 + tid] += sh[256 + tid + st]; }
        __syncthreads();
    }
    float mean = sh[0] / (float)N;
    float var  = sh[256] / (float)N - mean * mean;
    float inv  = rsqrtf(var + 1e-5f);
    for (int idx = tid; idx < N; idx += 256) {
        int r = idx >> logL, p = idx & (L - 1);
        int off = base + r * rstride + p;
        float v = data[off];
        v = (v - mean) * inv * gamma[chan0 + r] + beta[chan0 + r];
        data[off] = fmaxf(v, 0.f);
    }
}

// ---------------- transpose h[b][c][t] -> hT[(b,t)][c] ----------------
__global__ void transpose_h_kernel() {
    int b = blockIdx.z;
    int t0 = blockIdx.x * 32, c0 = blockIdx.y * 32;
    __shared__ float tile[32][33];
    int tx = threadIdx.x & 31, ty = threadIdx.x >> 5;  // 32x8
#pragma unroll
    for (int r = 0; r < 4; r++)
        tile[ty + r * 8][tx] = d_h[b * 65536 + (c0 + ty + r * 8) * 256 + t0 + tx];
    __syncthreads();
#pragma unroll
    for (int r = 0; r < 4; r++)
        d_hT[b * 65536 + (t0 + ty + r * 8) * 256 + c0 + tx] = tile[tx][ty + r * 8];
}

// ---------------- transpose r3d_w[o][c][n] -> WT[c][(n,o)] ----------------
__global__ void transpose_w_kernel(const float* __restrict__ w) {
    int c  = blockIdx.x;
    int o0 = blockIdx.y * 32;
    __shared__ float tile[32][33];
    int tid = threadIdx.x;  // 256
#pragma unroll
    for (int l = 0; l < 4; l++) {
        int e = tid + l * 256;
        int i = e >> 5, n = e & 31;           // i = o-local
        tile[i][n] = w[(size_t)(o0 + i) * 8192 + c * 32 + n];
    }
    __syncthreads();
#pragma unroll
    for (int l = 0; l < 4; l++) {
        int e = tid + l * 256;
        int n = e >> 5, i = e & 31;
        d_WT[(size_t)c * UCOLS + n * 512 + o0 + i] = tile[i][n];
    }
}

// ---------------- K3: extract sparse structure of sample_mask ----------------
__global__ void scan_mask_kernel(const float* __restrict__ mask) {
    int j = blockIdx.x * 256 + threadIdx.x;
    int idxs[8]; float vals[8];
    int cnt = 0;
    for (int tin = 0; tin < TSCALE; tin++) {
        float v = mask[tin * NTW + j];
        if (v != 0.f && cnt < 8) { idxs[cnt] = tin; vals[cnt] = v; cnt++; }
    }
#pragma unroll
    for (int s = 0; s < 8; s++) {
        d_midx[j * 8 + s] = (s < cnt) ? idxs[s] : 0;
        d_mval[j * 8 + s] = (s < cnt) ? vals[s] : 0.f;
    }
}

// ---------------- U-GEMM: U[512 x 16384] = hT[512 x 256] * WT[256 x 16384] ----------------
#define BM 128
#define BN 128
#define BK 32
#define STAGES 4
#define AS_STRIDE (BM * 36)
#define BS_STRIDE (BK * 132)
#define NKT (H1 / BK)          // 8 k-tiles

__device__ __forceinline__ void cp16(void* sdst, const void* gsrc) {
    unsigned saddr = (unsigned)__cvta_generic_to_shared(sdst);
    asm volatile("cp.async.cg.shared.global [%0], [%1], 16;\n"
                 :: "r"(saddr), "l"(gsrc));
}

__global__ void __launch_bounds__(256) u_gemm_kernel() {
    extern __shared__ float smem[];
    float* As = smem;
    float* Bs = smem + STAGES * AS_STRIDE;
    int m0 = blockIdx.x * BM;
    int n0 = blockIdx.y * BN;
    int tid = threadIdx.x;
    int warp = tid >> 5;
    int wm = warp & 1, wn = warp >> 1;

    wmma::fragment<wmma::accumulator, 16, 16, 8, float> acc[4][2];
#pragma unroll
    for (int i = 0; i < 4; i++)
#pragma unroll
        for (int j = 0; j < 2; j++) wmma::fill_fragment(acc[i][j], 0.f);

    auto issue = [&](int s, int kt) {
        int k0 = kt * BK;
        float* as = As + s * AS_STRIDE;
#pragma unroll
        for (int l = 0; l < 4; l++) {
            int q = tid + l * 256;
            int r = q >> 3, c = (q & 7) << 2;
            cp16(as + r * 36 + c, d_hT + (size_t)(m0 + r) * H1 + k0 + c);
        }
        float* bs = Bs + s * BS_STRIDE;
#pragma unroll
        for (int l = 0; l < 4; l++) {
            int q = tid + l * 256;
            int r = q >> 5, c = (q & 31) << 2;
            cp16(bs + r * 132 + c, d_WT + (size_t)(k0 + r) * UCOLS + n0 + c);
        }
        asm volatile("cp.async.commit_group;\n");
    };

#pragma unroll
    for (int s = 0; s < STAGES - 1; s++) issue(s, s);

    for (int kt = 0; kt < NKT; kt++) {
        asm volatile("cp.async.wait_group %0;\n" :: "n"(STAGES - 2));
        __syncthreads();
        int s = kt & (STAGES - 1);
        float* as = As + s * AS_STRIDE;
        float* bs = Bs + s * BS_STRIDE;
#pragma unroll
        for (int kk = 0; kk < BK; kk += 8) {
            wmma::fragment<wmma::matrix_a, 16, 16, 8, wmma::precision::tf32, wmma::row_major> af[4];
            wmma::fragment<wmma::matrix_b, 16, 16, 8, wmma::precision::tf32, wmma::row_major> bf[2];
#pragma unroll
            for (int i = 0; i < 4; i++)
                wmma::load_matrix_sync(af[i], as + (wm * 64 + i * 16) * 36 + kk, 36);
#pragma unroll
            for (int j = 0; j < 2; j++)
                wmma::load_matrix_sync(bf[j], bs + kk * 132 + wn * 32 + j * 16, 132);
#pragma unroll
            for (int i = 0; i < 4; i++)
#pragma unroll
                for (int j = 0; j < 2; j++)
                    wmma::mma_sync(acc[i][j], af[i], bf[j], acc[i][j]);
        }
        __syncthreads();
        if (kt + STAGES - 1 < NKT) issue((kt + STAGES - 1) & (STAGES - 1), kt + STAGES - 1);
    }
#pragma unroll
    for (int i = 0; i < 4; i++)
#pragma unroll
        for (int j = 0; j < 2; j++)
            wmma::store_matrix_sync(d_U + (size_t)(m0 + wm * 64 + i * 16) * UCOLS + n0 + wn * 32 + j * 16,
                                    acc[i][j], UCOLS, wmma::mem_row_major);
}

// ---------------- stage2: Y2[(b,t,w)][o] = sum_{n,s} val * U[(b,idx)][(n,o)] ----------------
__global__ void __launch_bounds__(256) stage2_kernel() {
    int t = blockIdx.x, b = blockIdx.y;
    int tid = threadIdx.x;
    __shared__ int   sidx[256][6];   // column c = n*8+w
    __shared__ float sval[256][6];
    {
        int n = tid >> 3, w = tid & 7;
        int jm = n * 2048 + t * 8 + w;
#pragma unroll
        for (int s = 0; s < 6; s++) {
            sidx[tid][s] = d_midx[jm * 8 + s];
            sval[tid][s] = d_mval[jm * 8 + s];
        }
    }
    __syncthreads();
    int w = tid >> 5, og = tid & 31;   // warp = one window, lane = o-group
    float4 acc[4];
#pragma unroll
    for (int p = 0; p < 4; p++) acc[p] = make_float4(0.f, 0.f, 0.f, 0.f);
    const float4* __restrict__ U4 = (const float4*)d_U;
    for (int n = 0; n < NS; n++) {
        int c = n * 8 + w;
#pragma unroll
        for (int s = 0; s < 6; s++) {
            float v = sval[c][s];          // warp-uniform
            if (v != 0.f) {
                int idx = sidx[c][s];
                size_t base4 = (size_t)(b * 256 + idx) * 4096 + n * 128 + og;
#pragma unroll
                for (int p = 0; p < 4; p++) {
                    float4 u = U4[base4 + p * 32];
                    acc[p].x += v * u.x; acc[p].y += v * u.y;
                    acc[p].z += v * u.z; acc[p].w += v * u.w;
                }
            }
        }
    }
    float4* Y4 = (float4*)d_Y;
    size_t ob = (size_t)(b * 2048 + t * 8 + w) * 128 + og;
#pragma unroll
    for (int p = 0; p < 4; p++) Y4[ob + p * 32] = acc[p];
}

// ---------------- GN3 (+r3d bias) + ReLU on Y2[(b,t,w)][o], in place ----------------
__global__ void gn3_kernel(const float* __restrict__ gamma,
                           const float* __restrict__ beta,
                           const float* __restrict__ bias) {
    int g = blockIdx.x;        // 32 groups of 16 o-channels
    int b = blockIdx.y;
    int tid = threadIdx.x;
    float s = 0.f, sq = 0.f;
    for (int it = 0; it < 128; it++) {
        int e = it * 256 + tid;
        int u = e & 15, tw = e >> 4;
        float v = d_Y[(size_t)(b * 2048 + tw) * 512 + g * 16 + u] + bias[g * 16 + u];
        s += v; sq += v * v;
    }
    __shared__ float sh[512];
    sh[tid] = s; sh[256 + tid] = sq;
    __syncthreads();
    for (int st = 128; st > 0; st >>= 1) {
        if (tid < st) { sh[tid] += sh[tid + st]; sh[256 + tid] += sh[256 + tid + st]; }
        __syncthreads();
    }
    float mean = sh[0] / 32768.f;
    float var  = sh[256] / 32768.f - mean * mean;
    float inv  = rsqrtf(var + 1e-5f);
    for (int it = 0; it < 128; it++) {
        int e = it * 256 + tid;
        int u = e & 15, tw = e >> 4;
        size_t off = (size_t)(b * 2048 + tw) * 512 + g * 16 + u;
        float v = d_Y[off] + bias[g * 16 + u];
        v = (v - mean) * inv * gamma[g * 16 + u] + beta[g * 16 + u];
        d_Y[off] = fmaxf(v, 0.f);
    }
}

// ---------------- r2d: F[h2][j] = sum_o W2[h2][o] * Y2[j][o]  + bias ----------------
__global__ void __launch_bounds__(256) r2d_kernel(const float* __restrict__ w2,
                                                  const float* __restrict__ b2) {
    int j0 = blockIdx.x * 32;
    int tid = threadIdx.x;
    int jl = tid & 31, hg = tid >> 5;   // lane = j (32), warp = h2-group (8)
    __shared__ float ys[32][65];
    __shared__ float ws[128][64];
    float acc[16];
#pragma unroll
    for (int u = 0; u < 16; u++) acc[u] = b2[hg * 16 + u];
    for (int oc = 0; oc < 512; oc += 64) {
        __syncthreads();
        for (int e = tid; e < 2048; e += 256) {
            int r = e >> 6, o = e & 63;
            ys[r][o] = d_Y[(size_t)(j0 + r) * 512 + oc + o];
        }
        for (int e = tid; e < 2048; e += 256) {
            int r = e >> 4, c4 = (e & 15) << 2;
            *(float4*)&ws[r][c4] = *(const float4*)&w2[r * 512 + oc + c4];
        }
        __syncthreads();
        for (int o = 0; o < 64; o++) {
            float yv = ys[jl][o];
#pragma unroll
            for (int u = 0; u < 16; u++)
                acc[u] += ws[hg * 16 + u][o] * yv;
        }
    }
#pragma unroll
    for (int u = 0; u < 16; u++)
        d_F[(hg * 16 + u) * JTOT + j0 + jl] = acc[u];
}

// ---------------- head conv3x3(128->128, same) + bias ----------------
__global__ void head_conv3_kernel(const float* __restrict__ w, const float* __restrict__ bias) {
    int t0 = blockIdx.x * 16;
    int o0 = blockIdx.y * 16;
    int b  = blockIdx.z;
    int tid = threadIdx.x;
    int tl = tid >> 3, wq = tid & 7;
    __shared__ float fs[4][18][10];
    __shared__ float ws[16][4][9];
    float acc[16];
#pragma unroll
    for (int o = 0; o < 16; o++) acc[o] = bias[o0 + o];
    for (int i0 = 0; i0 < H2; i0 += 4) {
        __syncthreads();
        for (int e = tid; e < 4 * 18 * 8; e += 128) {
            int ii = e / 144, rem = e % 144, tr = rem >> 3, wl = rem & 7;
            int tg = t0 - 1 + tr;
            float v = 0.f;
            if (tg >= 0 && tg < 256) v = d_F[(i0 + ii) * JTOT + b * 2048 + tg * 8 + wl];
            fs[ii][tr][1 + wl] = v;
        }
        for (int e = tid; e < 4 * 18 * 2; e += 128) {
            int ii = e / 36, rem = e % 36, tr = rem >> 1, side = rem & 1;
            fs[ii][tr][side ? 9 : 0] = 0.f;
        }
        for (int e = tid; e < 16 * 4 * 9; e += 128) {
            int o = e / 36, rem = e % 36, ii = rem / 9, kk = rem % 9;
            ws[o][ii][kk] = w[((o0 + o) * H2 + i0 + ii) * 9 + kk];
        }
        __syncthreads();
#pragma unroll
        for (int ii = 0; ii < 4; ii++) {
            float f00 = fs[ii][tl][wq],     f01 = fs[ii][tl][wq + 1],     f02 = fs[ii][tl][wq + 2];
            float f10 = fs[ii][tl + 1][wq], f11 = fs[ii][tl + 1][wq + 1], f12 = fs[ii][tl + 1][wq + 2];
            float f20 = fs[ii][tl + 2][wq], f21 = fs[ii][tl + 2][wq + 1], f22 = fs[ii][tl + 2][wq + 2];
#pragma unroll
            for (int o = 0; o < 16; o++) {
                const float* W9 = ws[o][ii];
                acc[o] += f00 * W9[0] + f01 * W9[1] + f02 * W9[2]
                        + f10 * W9[3] + f11 * W9[4] + f12 * W9[5]
                        + f20 * W9[6] + f21 * W9[7] + f22 * W9[8];
            }
        }
    }
    int t = t0 + tl;
#pragma unroll
    for (int o = 0; o < 16; o++)
        d_HT[(o0 + o) * JTOT + b * 2048 + t * 8 + wq] = acc[o];
}

// ---------------- head 1x1 -> sigmoid -> out ----------------
__global__ void head_final_kernel(const float* __restrict__ w2, const float* __restrict__ b2,
                                  float* __restrict__ out, int ch) {
    int j = blockIdx.x * 256 + threadIdx.x;
    float acc = b2[0];
    for (int i = 0; i < H2; i++) acc += w2[i] * d_HT[i * JTOT + j];
    float sg = 1.f / (1.f + expf(-acc));
    int b = j >> 11, rem = j & 2047;
    out[((b * 2 + ch) << 11) + rem] = sg;
}

// ---------------- launch ----------------
extern "C" void kernel_launch(void* const* d_in, const int* in_sizes, int n_in,
                              void* d_out, int out_size) {
    const float* x     = (const float*)d_in[0];
    const float* mask  = (const float*)d_in[1];
    const float* c1_w  = (const float*)d_in[2];
    const float* c1_b  = (const float*)d_in[3];
    const float* gn1_g = (const float*)d_in[4];
    const float* gn1_b = (const float*)d_in[5];
    const float* r3d_w = (const float*)d_in[6];
    const float* r3d_b = (const float*)d_in[7];
    const float* gn3_g = (const float*)d_in[8];
    const float* gn3_b = (const float*)d_in[9];
    const float* r2d_w = (const float*)d_in[10];
    const float* r2d_b = (const float*)d_in[11];
    const float* gn2_g = (const float*)d_in[12];
    const float* gn2_b = (const float*)d_in[13];
    const float* s1_w  = (const float*)d_in[14];
    const float* s1_b  = (const float*)d_in[15];
    const float* sgn_g = (const float*)d_in[16];
    const float* sgn_b = (const float*)d_in[17];
    const float* s2_w  = (const float*)d_in[18];
    const float* s2_b  = (const float*)d_in[19];
    const float* e1_w  = (const float*)d_in[20];
    const float* e1_b  = (const float*)d_in[21];
    const float* egn_g = (const float*)d_in[22];
    const float* egn_b = (const float*)d_in[23];
    const float* e2_w  = (const float*)d_in[24];
    const float* e2_b  = (const float*)d_in[25];
    float* out = (float*)d_out;

    static bool attr_set = false;
    const int gemm_smem = STAGES * (AS_STRIDE + BS_STRIDE) * (int)sizeof(float);
    if (!attr_set) {
        cudaFuncSetAttribute(u_gemm_kernel,
                             cudaFuncAttributeMaxDynamicSharedMemorySize, gemm_smem);
        attr_set = true;
    }

    // conv1 + GN1 + ReLU  -> d_h
    conv1_kernel<<<dim3(64, 2), 256>>>(x, c1_w, c1_b);
    gn_relu_kernel<<<64, 256>>>(0, gn1_g, gn1_b, 8, 8, TSCALE, H1 * TSCALE);

    // transposes + sparse mask structure
    transpose_h_kernel<<<dim3(8, 8, 2), 256>>>();
    transpose_w_kernel<<<dim3(256, 16), 256>>>(r3d_w);
    scan_mask_kernel<<<256, 256>>>(mask);

    // U-GEMM (c-contraction first), then sparse sampling contraction
    u_gemm_kernel<<<dim3(4, 128), 256, gemm_smem>>>();
    stage2_kernel<<<dim3(256, 2), 256>>>();

    // GN3(+bias)+ReLU on Y2
    gn3_kernel<<<dim3(32, 2), 256>>>(gn3_g, gn3_b, r3d_b);

    // r2d 1x1 -> d_F, GN2 + ReLU
    r2d_kernel<<<128, 256>>>(r2d_w, r2d_b);
    gn_relu_kernel<<<64, 256>>>(2, gn2_g, gn2_b, 4, 11, JTOT, 2048);

    // start head
    head_conv3_kernel<<<dim3(16, 8, 2), 128>>>(s1_w, s1_b);
    gn_relu_kernel<<<64, 256>>>(3, sgn_g, sgn_b, 4, 11, JTOT, 2048);
    head_final_kernel<<<16, 256>>>(s2_w, s2_b, out, 0);

    // end head
    head_conv3_kernel<<<dim3(16, 8, 2), 128>>>(e1_w, e1_b);
    gn_relu_kernel<<<64, 256>>>(3, egn_g, egn_b, 4, 11, JTOT, 2048);
    head_final_kernel<<<16, 256>>>(e2_w, e2_b, out, 1);
}

// round 5
// speedup vs baseline: 2.5860x; 1.2186x over previous
#include <cuda_runtime.h>
#include <mma.h>
using namespace nvcuda;

#define TSCALE 256
#define NS 32
#define NW 8
#define NTW 65536      // NS*TSCALE*NW
#define JTOT 4096      // B*TSCALE*NW
#define DIMX 512
#define H1 256
#define H3 512
#define H2 128
#define UCOLS 16384    // NS*H3

// ---------------- scratch (device globals; no runtime alloc) ----------------
__device__ float d_hT[2 * TSCALE * H1];         // [(b,t)][c], 512 KB
__device__ float d_WT[H1 * UCOLS];              // r3d_w transposed [c][(n,o)], 16.8 MB
__device__ float d_U[(size_t)512 * UCOLS];      // U[(b,tin)][(n,o)], 33.5 MB
__device__ int   d_midx[NTW * 8];
__device__ float d_mval[NTW * 8];
__device__ float d_Y[(size_t)JTOT * H3];        // Y2[(b,t,w)][o], 8 MB
__device__ float d_F[H2 * JTOT];                // r2d output [h2][j], 2 MB
__device__ float d_HT2[2][H2 * JTOT];           // head temps (start, end)

// ---------------- K0: fused conv1d(512->256,k=3) + GN1 + ReLU + transpose ----------------
// block = (group g, batch b); 256 threads (t). Each block owns one GN group (8 ch).
__global__ void __launch_bounds__(256) conv1_gn1_kernel(const float* __restrict__ x,
                                                        const float* __restrict__ w,
                                                        const float* __restrict__ bias,
                                                        const float* __restrict__ gamma,
                                                        const float* __restrict__ beta) {
    int g = blockIdx.x, b = blockIdx.y;
    int c0 = g * 8;
    int t = threadIdx.x;
    __shared__ float xs[8][TSCALE + 2];
    __shared__ float ws[8][8][3];
    float acc[8];
#pragma unroll
    for (int u = 0; u < 8; u++) acc[u] = bias[c0 + u];
    for (int i0 = 0; i0 < DIMX; i0 += 8) {
#pragma unroll
        for (int r = 0; r < 8; r++)
            xs[r][t + 1] = x[(b * DIMX + i0 + r) * TSCALE + t];
        if (t < 8) { xs[t][0] = 0.f; xs[t][TSCALE + 1] = 0.f; }
        if (t < 192) {
            int u = t / 24, rem = t % 24, r = rem / 3, k = rem % 3;
            ws[u][r][k] = w[(c0 + u) * (DIMX * 3) + (i0 + r) * 3 + k];
        }
        __syncthreads();
#pragma unroll
        for (int r = 0; r < 8; r++) {
            float xm = xs[r][t], x0 = xs[r][t + 1], xp = xs[r][t + 2];
#pragma unroll
            for (int u = 0; u < 8; u++)
                acc[u] += xm * ws[u][r][0] + x0 * ws[u][r][1] + xp * ws[u][r][2];
        }
        __syncthreads();
    }
    // GN over this block's 8 ch x 256 t = 2048 values
    float s = 0.f, sq = 0.f;
#pragma unroll
    for (int u = 0; u < 8; u++) { s += acc[u]; sq += acc[u] * acc[u]; }
    __shared__ float sh[512];
    sh[t] = s; sh[256 + t] = sq;
    __syncthreads();
    for (int st = 128; st > 0; st >>= 1) {
        if (t < st) { sh[t] += sh[t + st]; sh[256 + t] += sh[256 + t + st]; }
        __syncthreads();
    }
    float mean = sh[0] / 2048.f;
    float var  = sh[256] / 2048.f - mean * mean;
    float inv  = rsqrtf(var + 1e-5f);
    float v[8];
#pragma unroll
    for (int u = 0; u < 8; u++)
        v[u] = fmaxf((acc[u] - mean) * inv * gamma[c0 + u] + beta[c0 + u], 0.f);
    float* dst = &d_hT[(b * 256 + t) * 256 + c0];
    *(float4*)dst       = make_float4(v[0], v[1], v[2], v[3]);
    *(float4*)(dst + 4) = make_float4(v[4], v[5], v[6], v[7]);
}

// ---------------- transpose r3d_w[o][c][n] -> WT[c][(n,o)] ----------------
__global__ void transpose_w_kernel(const float* __restrict__ w) {
    int c  = blockIdx.x;
    int o0 = blockIdx.y * 32;
    __shared__ float tile[32][33];
    int tid = threadIdx.x;  // 256
#pragma unroll
    for (int l = 0; l < 4; l++) {
        int e = tid + l * 256;
        int i = e >> 5, n = e & 31;
        tile[i][n] = w[(size_t)(o0 + i) * 8192 + c * 32 + n];
    }
    __syncthreads();
#pragma unroll
    for (int l = 0; l < 4; l++) {
        int e = tid + l * 256;
        int n = e >> 5, i = e & 31;
        d_WT[(size_t)c * UCOLS + n * 512 + o0 + i] = tile[i][n];
    }
}

// ---------------- sparse structure of sample_mask ----------------
__global__ void scan_mask_kernel(const float* __restrict__ mask) {
    int j = blockIdx.x * 256 + threadIdx.x;
    int idxs[8]; float vals[8];
    int cnt = 0;
    for (int tin = 0; tin < TSCALE; tin++) {
        float v = mask[tin * NTW + j];
        if (v != 0.f && cnt < 8) { idxs[cnt] = tin; vals[cnt] = v; cnt++; }
    }
#pragma unroll
    for (int s = 0; s < 8; s++) {
        d_midx[j * 8 + s] = (s < cnt) ? idxs[s] : 0;
        d_mval[j * 8 + s] = (s < cnt) ? vals[s] : 0.f;
    }
}

// ---------------- U-GEMM: U[512 x 16384] = hT[512 x 256] * WT[256 x 16384] ----------------
#define BM 128
#define BN 128
#define BK 32
#define STAGES 2
#define AS_STRIDE (BM * 36)
#define BS_STRIDE (BK * 132)
#define NKT (H1 / BK)          // 8

__device__ __forceinline__ void cp16(void* sdst, const void* gsrc) {
    unsigned saddr = (unsigned)__cvta_generic_to_shared(sdst);
    asm volatile("cp.async.cg.shared.global [%0], [%1], 16;\n"
                 :: "r"(saddr), "l"(gsrc));
}

__global__ void __launch_bounds__(256) u_gemm_kernel() {
    extern __shared__ float smem[];
    float* As = smem;
    float* Bs = smem + STAGES * AS_STRIDE;
    int m0 = blockIdx.x * BM;
    int n0 = blockIdx.y * BN;
    int tid = threadIdx.x;
    int warp = tid >> 5;
    int wm = warp & 1, wn = warp >> 1;

    wmma::fragment<wmma::accumulator, 16, 16, 8, float> acc[4][2];
#pragma unroll
    for (int i = 0; i < 4; i++)
#pragma unroll
        for (int j = 0; j < 2; j++) wmma::fill_fragment(acc[i][j], 0.f);

    auto issue = [&](int s, int kt) {
        int k0 = kt * BK;
        float* as = As + s * AS_STRIDE;
#pragma unroll
        for (int l = 0; l < 4; l++) {
            int q = tid + l * 256;
            int r = q >> 3, c = (q & 7) << 2;
            cp16(as + r * 36 + c, d_hT + (size_t)(m0 + r) * H1 + k0 + c);
        }
        float* bs = Bs + s * BS_STRIDE;
#pragma unroll
        for (int l = 0; l < 4; l++) {
            int q = tid + l * 256;
            int r = q >> 5, c = (q & 31) << 2;
            cp16(bs + r * 132 + c, d_WT + (size_t)(k0 + r) * UCOLS + n0 + c);
        }
        asm volatile("cp.async.commit_group;\n");
    };

    issue(0, 0);
    for (int kt = 0; kt < NKT; kt++) {
        if (kt + 1 < NKT) {
            issue((kt + 1) & 1, kt + 1);
            asm volatile("cp.async.wait_group 1;\n");
        } else {
            asm volatile("cp.async.wait_group 0;\n");
        }
        __syncthreads();
        int s = kt & 1;
        float* as = As + s * AS_STRIDE;
        float* bs = Bs + s * BS_STRIDE;
#pragma unroll
        for (int kk = 0; kk < BK; kk += 8) {
            wmma::fragment<wmma::matrix_a, 16, 16, 8, wmma::precision::tf32, wmma::row_major> af[4];
            wmma::fragment<wmma::matrix_b, 16, 16, 8, wmma::precision::tf32, wmma::row_major> bf[2];
#pragma unroll
            for (int i = 0; i < 4; i++)
                wmma::load_matrix_sync(af[i], as + (wm * 64 + i * 16) * 36 + kk, 36);
#pragma unroll
            for (int j = 0; j < 2; j++)
                wmma::load_matrix_sync(bf[j], bs + kk * 132 + wn * 32 + j * 16, 132);
#pragma unroll
            for (int i = 0; i < 4; i++)
#pragma unroll
                for (int j = 0; j < 2; j++)
                    wmma::mma_sync(acc[i][j], af[i], bf[j], acc[i][j]);
        }
        __syncthreads();
    }
#pragma unroll
    for (int i = 0; i < 4; i++)
#pragma unroll
        for (int j = 0; j < 2; j++)
            wmma::store_matrix_sync(d_U + (size_t)(m0 + wm * 64 + i * 16) * UCOLS + n0 + wn * 32 + j * 16,
                                    acc[i][j], UCOLS, wmma::mem_row_major);
}

// ---------------- stage2: Y2[(b,t,w)][o] = sum_{n,s} val * U[(b,idx)][(n,o)] ----------------
__global__ void __launch_bounds__(256) stage2_kernel() {
    int t = blockIdx.x, b = blockIdx.y;
    int tid = threadIdx.x;
    __shared__ int   sidx[256][6];
    __shared__ float sval[256][6];
    {
        int n = tid >> 3, w = tid & 7;
        int jm = n * 2048 + t * 8 + w;
#pragma unroll
        for (int s = 0; s < 6; s++) {
            sidx[tid][s] = d_midx[jm * 8 + s];
            sval[tid][s] = d_mval[jm * 8 + s];
        }
    }
    __syncthreads();
    int w = tid >> 5, og = tid & 31;
    float4 acc[4];
#pragma unroll
    for (int p = 0; p < 4; p++) acc[p] = make_float4(0.f, 0.f, 0.f, 0.f);
    const float4* __restrict__ U4 = (const float4*)d_U;
    for (int n = 0; n < NS; n++) {
        int c = n * 8 + w;
#pragma unroll
        for (int s = 0; s < 6; s++) {
            float v = sval[c][s];
            if (v != 0.f) {
                int idx = sidx[c][s];
                size_t base4 = (size_t)(b * 256 + idx) * 4096 + n * 128 + og;
#pragma unroll
                for (int p = 0; p < 4; p++) {
                    float4 u = U4[base4 + p * 32];
                    acc[p].x += v * u.x; acc[p].y += v * u.y;
                    acc[p].z += v * u.z; acc[p].w += v * u.w;
                }
            }
        }
    }
    float4* Y4 = (float4*)d_Y;
    size_t ob = (size_t)(b * 2048 + t * 8 + w) * 128 + og;
#pragma unroll
    for (int p = 0; p < 4; p++) Y4[ob + p * 32] = acc[p];
}

// ---------------- GN3 (+r3d bias) + ReLU on Y2[(b,t,w)][o] ----------------
__global__ void gn3_kernel(const float* __restrict__ gamma,
                           const float* __restrict__ beta,
                           const float* __restrict__ bias) {
    int g = blockIdx.x, b = blockIdx.y;
    int tid = threadIdx.x;
    float s = 0.f, sq = 0.f;
    for (int it = 0; it < 128; it++) {
        int e = it * 256 + tid;
        int u = e & 15, tw = e >> 4;
        float v = d_Y[(size_t)(b * 2048 + tw) * 512 + g * 16 + u] + bias[g * 16 + u];
        s += v; sq += v * v;
    }
    __shared__ float sh[512];
    sh[tid] = s; sh[256 + tid] = sq;
    __syncthreads();
    for (int st = 128; st > 0; st >>= 1) {
        if (tid < st) { sh[tid] += sh[tid + st]; sh[256 + tid] += sh[256 + tid + st]; }
        __syncthreads();
    }
    float mean = sh[0] / 32768.f;
    float var  = sh[256] / 32768.f - mean * mean;
    float inv  = rsqrtf(var + 1e-5f);
    for (int it = 0; it < 128; it++) {
        int e = it * 256 + tid;
        int u = e & 15, tw = e >> 4;
        size_t off = (size_t)(b * 2048 + tw) * 512 + g * 16 + u;
        float v = d_Y[off] + bias[g * 16 + u];
        v = (v - mean) * inv * gamma[g * 16 + u] + beta[g * 16 + u];
        d_Y[off] = fmaxf(v, 0.f);
    }
}

// ---------------- r2d: F[h2][j] = sum_o W2[h2][o] * Y2[j][o] + bias ----------------
// grid (16 j-tiles, 8 h-groups), 256 threads (j). Weights float4 from smem.
__global__ void __launch_bounds__(256) r2d_kernel(const float* __restrict__ w2,
                                                  const float* __restrict__ b2) {
    int j = blockIdx.x * 256 + threadIdx.x;
    int h0 = blockIdx.y * 16;
    __shared__ __align__(16) float ws[512][16];   // [o][u] 32 KB
    for (int e = threadIdx.x; e < 512 * 4; e += 256) {
        int o = e >> 2, u4 = (e & 3) * 4;
#pragma unroll
        for (int q = 0; q < 4; q++)
            ws[o][u4 + q] = w2[(h0 + u4 + q) * 512 + o];
    }
    __syncthreads();
    float4 acc[4];
#pragma unroll
    for (int p = 0; p < 4; p++)
        acc[p] = make_float4(b2[h0 + p * 4], b2[h0 + p * 4 + 1], b2[h0 + p * 4 + 2], b2[h0 + p * 4 + 3]);
    const float* __restrict__ yrow = &d_Y[(size_t)j * 512];
    for (int o = 0; o < 512; o++) {
        float yv = yrow[o];
        const float4* w4 = (const float4*)ws[o];
#pragma unroll
        for (int p = 0; p < 4; p++) {
            float4 ww = w4[p];
            acc[p].x += ww.x * yv; acc[p].y += ww.y * yv;
            acc[p].z += ww.z * yv; acc[p].w += ww.w * yv;
        }
    }
#pragma unroll
    for (int p = 0; p < 4; p++) {
        d_F[(h0 + p * 4 + 0) * JTOT + j] = acc[p].x;
        d_F[(h0 + p * 4 + 1) * JTOT + j] = acc[p].y;
        d_F[(h0 + p * 4 + 2) * JTOT + j] = acc[p].z;
        d_F[(h0 + p * 4 + 3) * JTOT + j] = acc[p].w;
    }
}

// ---------------- GN2 + ReLU on d_F [h2][j] ----------------
__global__ void gn2_kernel(const float* __restrict__ gamma, const float* __restrict__ beta) {
    int g = blockIdx.x & 31;
    int b = blockIdx.x >> 5;
    int chan0 = g * 4;
    int base = chan0 * JTOT + b * 2048;
    int tid = threadIdx.x;
    float s = 0.f, sq = 0.f;
    for (int idx = tid; idx < 8192; idx += 256) {
        int r = idx >> 11, p = idx & 2047;
        float v = d_F[base + r * JTOT + p];
        s += v; sq += v * v;
    }
    __shared__ float sh[512];
    sh[tid] = s; sh[256 + tid] = sq;
    __syncthreads();
    for (int st = 128; st > 0; st >>= 1) {
        if (tid < st) { sh[tid] += sh[tid + st]; sh[256 + tid] += sh[256 + tid + st]; }
        __syncthreads();
    }
    float mean = sh[0] / 8192.f;
    float var  = sh[256] / 8192.f - mean * mean;
    float inv  = rsqrtf(var + 1e-5f);
    for (int idx = tid; idx < 8192; idx += 256) {
        int r = idx >> 11, p = idx & 2047;
        int off = base + r * JTOT + p;
        float v = (d_F[off] - mean) * inv * gamma[chan0 + r] + beta[chan0 + r];
        d_F[off] = fmaxf(v, 0.f);
    }
}

// ---------------- heads conv3x3(128->128) + bias, both heads one launch ----------------
// grid (8 t-tiles of 32, 8 o-tiles of 16, 4 = head*2+b); 256 threads = (tl32, wq8)
__global__ void __launch_bounds__(256) head_conv3_kernel(const float* __restrict__ ws_,
                                                         const float* __restrict__ bs_,
                                                         const float* __restrict__ we_,
                                                         const float* __restrict__ be_) {
    int t0 = blockIdx.x * 32;
    int o0 = blockIdx.y * 16;
    int head = blockIdx.z >> 1, b = blockIdx.z & 1;
    const float* w    = head ? we_ : ws_;
    const float* bias = head ? be_ : bs_;
    int tid = threadIdx.x;
    int tl = tid >> 3, wq = tid & 7;
    __shared__ float fs[4][34][10];
    __shared__ __align__(16) float ws[4][9][16];
    float4 acc[4];
    {
        const float4* b4 = (const float4*)&bias[o0];
#pragma unroll
        for (int p = 0; p < 4; p++) acc[p] = b4[p];
    }
    for (int i0 = 0; i0 < H2; i0 += 4) {
        __syncthreads();
        // interior fill: 4 ch x 34 t-rows x 8 w = 1088
        for (int e = tid; e < 1088; e += 256) {
            int ii = e >> 8;          // e/272 approx: use exact below
            ii = e / 272; int rem = e % 272;
            int tr = rem >> 3, wl = rem & 7;
            int tg = t0 - 1 + tr;
            float v = 0.f;
            if (tg >= 0 && tg < 256) v = d_F[(i0 + ii) * JTOT + b * 2048 + tg * 8 + wl];
            fs[ii][tr][1 + wl] = v;
        }
        // w-edges zero: 4 x 34 x 2 = 272
        for (int e = tid; e < 272; e += 256) {
            int ii = e / 68, rem = e % 68;
            int tr = rem >> 1, side = rem & 1;
            fs[ii][tr][side * 9] = 0.f;
        }
        // weights -> [ii][kk][o]
        for (int e = tid; e < 576; e += 256) {
            int o = e & 15, rem = e >> 4;
            int kk = rem % 9, ii = rem / 9;
            ws[ii][kk][o] = w[(o0 + o) * (H2 * 9) + (i0 + ii) * 9 + kk];
        }
        __syncthreads();
#pragma unroll
        for (int ii = 0; ii < 4; ii++) {
            float f[9];
#pragma unroll
            for (int dt = 0; dt < 3; dt++)
#pragma unroll
                for (int dw = 0; dw < 3; dw++)
                    f[dt * 3 + dw] = fs[ii][tl + dt][wq + dw];
#pragma unroll
            for (int kk = 0; kk < 9; kk++) {
                float fv = f[kk];
                const float4* w4 = (const float4*)ws[ii][kk];
#pragma unroll
                for (int p = 0; p < 4; p++) {
                    float4 ww = w4[p];
                    acc[p].x += fv * ww.x; acc[p].y += fv * ww.y;
                    acc[p].z += fv * ww.z; acc[p].w += fv * ww.w;
                }
            }
        }
    }
    int jout = b * 2048 + (t0 + tl) * 8 + wq;
#pragma unroll
    for (int p = 0; p < 4; p++) {
        d_HT2[head][(o0 + p * 4 + 0) * JTOT + jout] = acc[p].x;
        d_HT2[head][(o0 + p * 4 + 1) * JTOT + jout] = acc[p].y;
        d_HT2[head][(o0 + p * 4 + 2) * JTOT + jout] = acc[p].z;
        d_HT2[head][(o0 + p * 4 + 3) * JTOT + jout] = acc[p].w;
    }
}

// ---------------- GN + ReLU for both heads ----------------
__global__ void gn_heads_kernel(const float* __restrict__ gs, const float* __restrict__ bs_,
                                const float* __restrict__ ge, const float* __restrict__ be_) {
    int g = blockIdx.x, b = blockIdx.y, head = blockIdx.z;
    const float* gamma = head ? ge : gs;
    const float* beta  = head ? be_ : bs_;
    float* data = d_HT2[head];
    int chan0 = g * 4;
    int base = chan0 * JTOT + b * 2048;
    int tid = threadIdx.x;
    float s = 0.f, sq = 0.f;
    for (int idx = tid; idx < 8192; idx += 256) {
        int r = idx >> 11, p = idx & 2047;
        float v = data[base + r * JTOT + p];
        s += v; sq += v * v;
    }
    __shared__ float sh[512];
    sh[tid] = s; sh[256 + tid] = sq;
    __syncthreads();
    for (int st = 128; st > 0; st >>= 1) {
        if (tid < st) { sh[tid] += sh[tid + st]; sh[256 + tid] += sh[256 + tid + st]; }
        __syncthreads();
    }
    float mean = sh[0] / 8192.f;
    float var  = sh[256] / 8192.f - mean * mean;
    float inv  = rsqrtf(var + 1e-5f);
    for (int idx = tid; idx < 8192; idx += 256) {
        int r = idx >> 11, p = idx & 2047;
        int off = base + r * JTOT + p;
        float v = (data[off] - mean) * inv * gamma[chan0 + r] + beta[chan0 + r];
        data[off] = fmaxf(v, 0.f);
    }
}

// ---------------- both heads: 1x1 -> sigmoid -> out ----------------
__global__ void head_final_kernel(const float* __restrict__ ws2, const float* __restrict__ bs2,
                                  const float* __restrict__ we2, const float* __restrict__ be2,
                                  float* __restrict__ out) {
    int j = blockIdx.x * 256 + threadIdx.x;
    int head = blockIdx.y;
    const float* w2 = head ? we2 : ws2;
    float acc = head ? be2[0] : bs2[0];
    const float* data = d_HT2[head];
    for (int i = 0; i < H2; i++) acc += w2[i] * data[i * JTOT + j];
    float sg = 1.f / (1.f + expf(-acc));
    int b = j >> 11, rem = j & 2047;
    out[((b * 2 + head) << 11) + rem] = sg;
}

// ---------------- launch ----------------
extern "C" void kernel_launch(void* const* d_in, const int* in_sizes, int n_in,
                              void* d_out, int out_size) {
    const float* x     = (const float*)d_in[0];
    const float* mask  = (const float*)d_in[1];
    const float* c1_w  = (const float*)d_in[2];
    const float* c1_b  = (const float*)d_in[3];
    const float* gn1_g = (const float*)d_in[4];
    const float* gn1_b = (const float*)d_in[5];
    const float* r3d_w = (const float*)d_in[6];
    const float* r3d_b = (const float*)d_in[7];
    const float* gn3_g = (const float*)d_in[8];
    const float* gn3_b = (const float*)d_in[9];
    const float* r2d_w = (const float*)d_in[10];
    const float* r2d_b = (const float*)d_in[11];
    const float* gn2_g = (const float*)d_in[12];
    const float* gn2_b = (const float*)d_in[13];
    const float* s1_w  = (const float*)d_in[14];
    const float* s1_b  = (const float*)d_in[15];
    const float* sgn_g = (const float*)d_in[16];
    const float* sgn_b = (const float*)d_in[17];
    const float* s2_w  = (const float*)d_in[18];
    const float* s2_b  = (const float*)d_in[19];
    const float* e1_w  = (const float*)d_in[20];
    const float* e1_b  = (const float*)d_in[21];
    const float* egn_g = (const float*)d_in[22];
    const float* egn_b = (const float*)d_in[23];
    const float* e2_w  = (const float*)d_in[24];
    const float* e2_b  = (const float*)d_in[25];
    float* out = (float*)d_out;

    static bool attr_set = false;
    const int gemm_smem = STAGES * (AS_STRIDE + BS_STRIDE) * (int)sizeof(float);
    if (!attr_set) {
        cudaFuncSetAttribute(u_gemm_kernel,
                             cudaFuncAttributeMaxDynamicSharedMemorySize, gemm_smem);
        attr_set = true;
    }

    // 0: fused conv1+GN1+ReLU -> d_hT
    conv1_gn1_kernel<<<dim3(32, 2), 256>>>(x, c1_w, c1_b, gn1_g, gn1_b);
    // 1: weight transpose
    transpose_w_kernel<<<dim3(256, 16), 256>>>(r3d_w);
    // 2: sparse mask structure
    scan_mask_kernel<<<256, 256>>>(mask);
    // 3: U-GEMM (profiled slot)
    u_gemm_kernel<<<dim3(4, 128), 256, gemm_smem>>>();
    // 4: sparse sampling contraction
    stage2_kernel<<<dim3(256, 2), 256>>>();
    // 5: GN3(+bias)+ReLU
    gn3_kernel<<<dim3(32, 2), 256>>>(gn3_g, gn3_b, r3d_b);
    // 6: r2d 1x1
    r2d_kernel<<<dim3(16, 8), 256>>>(r2d_w, r2d_b);
    // 7: GN2
    gn2_kernel<<<64, 256>>>(gn2_g, gn2_b);
    // 8: both heads conv3x3
    head_conv3_kernel<<<dim3(8, 8, 4), 256>>>(s1_w, s1_b, e1_w, e1_b);
    // 9: both heads GN
    gn_heads_kernel<<<dim3(32, 2, 2), 256>>>(sgn_g, sgn_b, egn_g, egn_b);
    // 10: both heads final
    head_final_kernel<<<dim3(16, 2), 256>>>(s2_w, s2_b, e2_w, e2_b, out);
}